// round 11
// baseline (speedup 1.0000x reference)
#include <cuda_runtime.h>
#include <cstdint>

// Problem constants
#define E_   1024
#define H_   16
#define D_   64
#define B_   4
#define NQ_  4096
#define NK_  4096
#define MTOT (B_*NQ_)      // 16384 rows for all projections
#define BH_  (B_*H_)       // 64
#define NSPLIT 32          // split-K partitions for KV reduction

// ---------------- scratch (device globals; no allocation APIs) ----------------
__device__ float g_q[(size_t)MTOT * E_];      // raw Q projection (pre-LN)
__device__ float g_k[(size_t)MTOT * E_];      // raw K projection (pre-LN)
__device__ float g_v[(size_t)MTOT * E_];
__device__ float g_attn[(size_t)MTOT * E_];
__device__ float g_kvp[(size_t)NSPLIT * BH_ * D_ * D_];
__device__ float g_ksp[(size_t)NSPLIT * BH_ * D_];
__device__ float g_kv[(size_t)BH_ * D_ * D_];
__device__ float g_ksum[(size_t)BH_ * D_];
__device__ float g_kstats[(size_t)2 * MTOT];  // per-row {sum, sumsq} of K proj
__device__ float g_qstats[(size_t)2 * MTOT];  // per-row {sum, sumsq} of Q proj

// =====================================================================
// Helpers (sm_80+ base target features only)
// =====================================================================
__device__ __forceinline__ uint32_t smem_u32(const void* p) {
    uint32_t a;
    asm("{ .reg .u64 t; cvta.to.shared.u64 t, %1; cvt.u32.u64 %0, t; }"
        : "=r"(a) : "l"(p));
    return a;
}

__device__ __forceinline__ void cp_async16(uint32_t saddr, const void* gaddr) {
    asm volatile("cp.async.cg.shared.global [%0], [%1], 16;"
                 :: "r"(saddr), "l"(gaddr));
}
__device__ __forceinline__ void cp_commit() {
    asm volatile("cp.async.commit_group;" ::: "memory");
}
template <int N>
__device__ __forceinline__ void cp_wait() {
    asm volatile("cp.async.wait_group %0;" :: "n"(N) : "memory");
}

__device__ __forceinline__ uint32_t f2tf32(float f) {
    uint32_t u;
    asm("cvt.rna.tf32.f32 %0, %1;" : "=r"(u) : "f"(f));
    return u;
}

__device__ __forceinline__ void mma_tf32(
    float& d0, float& d1, float& d2, float& d3,
    uint32_t a0, uint32_t a1, uint32_t a2, uint32_t a3,
    uint32_t b0, uint32_t b1)
{
    asm volatile(
        "mma.sync.aligned.m16n8k8.row.col.f32.tf32.tf32.f32 "
        "{%0,%1,%2,%3}, {%4,%5,%6,%7}, {%8,%9}, {%0,%1,%2,%3};"
        : "+f"(d0), "+f"(d1), "+f"(d2), "+f"(d3)
        : "r"(a0), "r"(a1), "r"(a2), "r"(a3), "r"(b0), "r"(b1));
}

// =====================================================================
// tf32 GEMM body (round-7 mainloop, exact): C[m,n]=sum_k X[m,k]W[n,k]+bias[n]
// Optional stats: per-row {sum,sumsq} of outputs atomically accumulated.
// =====================================================================
#define BM 128
#define BN 128
#define BK 32
#define NKT (E_/BK)
#define ASTR 36
#define TILEF (128*ASTR)
#define GEMM_SMEM (4*TILEF*4)   // 73728 bytes
#define NGEMM_CTAS 1024

__device__ __forceinline__ void gemm_body(
    const float* __restrict__ X, const float* __restrict__ W,
    const float* __restrict__ bias, float* __restrict__ C,
    float* __restrict__ stats, int bmId, int bnId)
{
    extern __shared__ float smf[];
    const uint32_t sbase = smem_u32(smf);
    const int tid = threadIdx.x;
    const int wid = tid >> 5;
    const int lane = tid & 31;
    const int g  = lane >> 2;
    const int t4 = lane & 3;
    const int wm = (wid >> 2) * 64;
    const int wn = (wid & 3) * 32;
    const int bm = bmId * BM;
    const int bn = bnId * BN;

    const int srow = tid >> 3;
    const int sc4  = (tid & 7) * 4;

    float acc[4][4][4];
#pragma unroll
    for (int i = 0; i < 4; i++)
#pragma unroll
        for (int j = 0; j < 4; j++)
#pragma unroll
            for (int r = 0; r < 4; r++) acc[i][j][r] = 0.0f;

    auto prefetch = [&](int kt, int buf) {
        const int k0 = kt * BK;
        const uint32_t aoff = sbase + (uint32_t)(buf * TILEF) * 4u;
        const uint32_t boff = sbase + (uint32_t)((2 + buf) * TILEF) * 4u;
#pragma unroll
        for (int l = 0; l < 4; l++) {
            int row = srow + l * 32;
            cp_async16(aoff + (row * ASTR + sc4) * 4,
                       X + (size_t)(bm + row) * E_ + k0 + sc4);
            cp_async16(boff + (row * ASTR + sc4) * 4,
                       W + (size_t)(bn + row) * E_ + k0 + sc4);
        }
        cp_commit();
    };

    prefetch(0, 0);

    for (int kt = 0; kt < NKT; kt++) {
        const int buf = kt & 1;
        if (kt + 1 < NKT) {
            prefetch(kt + 1, buf ^ 1);
            cp_wait<1>();
        } else {
            cp_wait<0>();
        }
        __syncthreads();

        const float* As = smf + buf * TILEF;
        const float* Bs = smf + (2 + buf) * TILEF;

#pragma unroll
        for (int ks = 0; ks < 4; ks++) {
            const int kk = ks * 8;
            uint32_t bf[4][2];
#pragma unroll
            for (int nf = 0; nf < 4; nf++) {
                const float* bp = Bs + (wn + nf * 8 + g) * ASTR + kk + t4;
                bf[nf][0] = f2tf32(bp[0]);
                bf[nf][1] = f2tf32(bp[4]);
            }
#pragma unroll
            for (int mf = 0; mf < 4; mf++) {
                const float* ap = As + (wm + mf * 16 + g) * ASTR + kk + t4;
                uint32_t a0 = f2tf32(ap[0]);
                uint32_t a1 = f2tf32(ap[8 * ASTR]);
                uint32_t a2 = f2tf32(ap[4]);
                uint32_t a3 = f2tf32(ap[8 * ASTR + 4]);
#pragma unroll
                for (int nf = 0; nf < 4; nf++)
                    mma_tf32(acc[mf][nf][0], acc[mf][nf][1],
                             acc[mf][nf][2], acc[mf][nf][3],
                             a0, a1, a2, a3, bf[nf][0], bf[nf][1]);
            }
        }
        __syncthreads();
    }

    // Epilogue: bias add + stores; optional row-stat accumulation
    float rs[8], rq[8];
#pragma unroll
    for (int i = 0; i < 8; i++) { rs[i] = 0.0f; rq[i] = 0.0f; }

#pragma unroll
    for (int nf = 0; nf < 4; nf++) {
        const int col = bn + wn + nf * 8 + t4 * 2;
        const float2 b2 = *(const float2*)(bias + col);
#pragma unroll
        for (int mf = 0; mf < 4; mf++) {
            const int row0 = bm + wm + mf * 16 + g;
            float2 v0, v1;
            v0.x = acc[mf][nf][0] + b2.x;
            v0.y = acc[mf][nf][1] + b2.y;
            v1.x = acc[mf][nf][2] + b2.x;
            v1.y = acc[mf][nf][3] + b2.y;
            *(float2*)(C + (size_t)row0 * E_ + col) = v0;
            *(float2*)(C + (size_t)(row0 + 8) * E_ + col) = v1;
            rs[mf * 2 + 0] += v0.x + v0.y;
            rq[mf * 2 + 0] += v0.x * v0.x + v0.y * v0.y;
            rs[mf * 2 + 1] += v1.x + v1.y;
            rq[mf * 2 + 1] += v1.x * v1.x + v1.y * v1.y;
        }
    }

    if (stats) {
        // butterfly over the 4 lanes sharing each row (t4 = lane&3)
#pragma unroll
        for (int o = 1; o < 4; o <<= 1) {
#pragma unroll
            for (int i = 0; i < 8; i++) {
                rs[i] += __shfl_xor_sync(0xffffffffu, rs[i], o);
                rq[i] += __shfl_xor_sync(0xffffffffu, rq[i], o);
            }
        }
        if (t4 == 0) {
#pragma unroll
            for (int i = 0; i < 8; i++) {
                int row = bm + wm + (i >> 1) * 16 + (i & 1) * 8 + g;
                atomicAdd(&stats[2 * row + 0], rs[i]);
                atomicAdd(&stats[2 * row + 1], rq[i]);
            }
        }
    }
}

// ---------------- KV reduction body with inline LN+elu on K ----------------
__device__ __forceinline__ void kv_body(int bh, int split,
                                        const float* __restrict__ gk,
                                        const float* __restrict__ betak)
{
    const int b = bh >> 4, h = bh & 15;
    const int t = threadIdx.x;
    const int tx = t & 15, ty = t >> 4;

    __shared__ float Ks[64][68];
    __shared__ float Vs[64][68];
    __shared__ float mu_s[64], rstd_s[64], gam_s[64], bet_s[64];

    const float* kbase = g_k + (size_t)(b * NK_) * E_ + h * D_;
    const float* vbase = g_v + (size_t)(b * NK_) * E_ + h * D_;

    if (t < 64) {
        gam_s[t] = gk[h * D_ + t];
        bet_s[t] = betak[h * D_ + t];
    }

    float acc[4][4];
#pragma unroll
    for (int i = 0; i < 4; i++)
#pragma unroll
        for (int j = 0; j < 4; j++) acc[i][j] = 0.0f;
    float ks_local = 0.0f;

    for (int sblk = 0; sblk < 2; sblk++) {
        int n0 = split * 128 + sblk * 64;
        if (t < 64) {
            int row = b * NK_ + n0 + t;
            float s = g_kstats[2 * row + 0];
            float q = g_kstats[2 * row + 1];
            float mu = s * (1.0f / E_);
            float var = q * (1.0f / E_) - mu * mu;
            mu_s[t] = mu;
            rstd_s[t] = rsqrtf(var + 1e-5f);
        }
        __syncthreads();
#pragma unroll
        for (int l = 0; l < 4; l++) {
            int lin = t + l * 256;
            int r = lin >> 4;
            int c4 = (lin & 15) * 4;
            float4 kx = *(const float4*)(kbase + (size_t)(n0 + r) * E_ + c4);
            float mu = mu_s[r], rstd = rstd_s[r];
            float y0 = (kx.x - mu) * rstd * gam_s[c4 + 0] + bet_s[c4 + 0];
            float y1 = (kx.y - mu) * rstd * gam_s[c4 + 1] + bet_s[c4 + 1];
            float y2 = (kx.z - mu) * rstd * gam_s[c4 + 2] + bet_s[c4 + 2];
            float y3 = (kx.w - mu) * rstd * gam_s[c4 + 3] + bet_s[c4 + 3];
            float4 kz;
            kz.x = (y0 > 0.0f) ? (y0 + 1.0f) : expf(y0);
            kz.y = (y1 > 0.0f) ? (y1 + 1.0f) : expf(y1);
            kz.z = (y2 > 0.0f) ? (y2 + 1.0f) : expf(y2);
            kz.w = (y3 > 0.0f) ? (y3 + 1.0f) : expf(y3);
            *(float4*)&Ks[r][c4] = kz;
            *(float4*)&Vs[r][c4] = *(const float4*)(vbase + (size_t)(n0 + r) * E_ + c4);
        }
        __syncthreads();
#pragma unroll 4
        for (int n = 0; n < 64; n++) {
            float a[4], bb[4];
            *(float4*)a  = *(const float4*)&Ks[n][ty * 4];
            *(float4*)bb = *(const float4*)&Vs[n][tx * 4];
#pragma unroll
            for (int i = 0; i < 4; i++)
#pragma unroll
                for (int j = 0; j < 4; j++)
                    acc[i][j] += a[i] * bb[j];
        }
        if (t < 64) {
            float ss = 0.0f;
#pragma unroll 4
            for (int n = 0; n < 64; n++) ss += Ks[n][t];
            ks_local += ss;
        }
        __syncthreads();
    }

    float* outp = g_kvp + ((size_t)(split * BH_ + bh)) * (D_ * D_);
#pragma unroll
    for (int i = 0; i < 4; i++)
#pragma unroll
        for (int j = 0; j < 4; j++)
            outp[(ty * 4 + i) * D_ + tx * 4 + j] = acc[i][j];
    if (t < 64) g_ksp[(size_t)(split * BH_ + bh) * D_ + t] = ks_local;
}

// =====================================================================
// Kernels
// =====================================================================
__global__ void __launch_bounds__(256, 2)
gemm_plain_kernel(const float* __restrict__ X, const float* __restrict__ W,
                  const float* __restrict__ bias, float* __restrict__ C)
{
    gemm_body(X, W, bias, C, nullptr, blockIdx.x & 127, blockIdx.x >> 7);
}

__global__ void __launch_bounds__(256, 2)
gemm_stats_kernel(const float* __restrict__ X, const float* __restrict__ W,
                  const float* __restrict__ bias, float* __restrict__ C,
                  float* __restrict__ stats)
{
    gemm_body(X, W, bias, C, stats, blockIdx.x & 127, blockIdx.x >> 7);
}

// Q-projection GEMM (ids < 1024) ∥ KV split-K partials (ids >= 1024)
__global__ void __launch_bounds__(256, 2)
gemm_stats_kv_kernel(const float* __restrict__ X, const float* __restrict__ W,
                     const float* __restrict__ bias, float* __restrict__ C,
                     float* __restrict__ stats,
                     const float* __restrict__ gk, const float* __restrict__ betak)
{
    if (blockIdx.x < NGEMM_CTAS) {
        gemm_body(X, W, bias, C, stats, blockIdx.x & 127, blockIdx.x >> 7);
    } else {
        int id = blockIdx.x - NGEMM_CTAS;
        kv_body(id & 63, id >> 6, gk, betak);
    }
}

// ---------------- reduce split-K partials ----------------
__global__ __launch_bounds__(256)
void reduce_kv_kernel() {
    int idx = blockIdx.x * blockDim.x + threadIdx.x;
    const int NKV = BH_ * D_ * D_;
    const int NKS = BH_ * D_;
    if (idx < NKV) {
        float s = 0.0f;
#pragma unroll
        for (int sp = 0; sp < NSPLIT; sp++)
            s += g_kvp[(size_t)sp * NKV + idx];
        g_kv[idx] = s;
    } else if (idx < NKV + NKS) {
        int j = idx - NKV;
        float s = 0.0f;
#pragma unroll
        for (int sp = 0; sp < NSPLIT; sp++)
            s += g_ksp[(size_t)sp * NKS + j];
        g_ksum[j] = s;
    }
}

// ---------------- attention apply with inline LN+elu on Q ----------------
__global__ __launch_bounds__(128)
void attn_kernel(const float* __restrict__ gq, const float* __restrict__ betaq)
{
    const int bh = blockIdx.x;
    const int b = bh >> 4, h = bh & 15;
    const int n0 = blockIdx.y * 64;
    const int t = threadIdx.x;

    __shared__ float Qs[64][68];
    __shared__ float KVs[64][68];
    __shared__ float ksums[64];
    __shared__ float mu_s[64], rstd_s[64], gam_s[64], bet_s[64];

    if (t < 64) {
        int row = b * NQ_ + n0 + t;
        float s = g_qstats[2 * row + 0];
        float q = g_qstats[2 * row + 1];
        float mu = s * (1.0f / E_);
        float var = q * (1.0f / E_) - mu * mu;
        mu_s[t] = mu;
        rstd_s[t] = rsqrtf(var + 1e-5f);
        gam_s[t] = gq[h * D_ + t];
        bet_s[t] = betaq[h * D_ + t];
        ksums[t] = g_ksum[(size_t)bh * D_ + t];
    }
    __syncthreads();

#pragma unroll
    for (int l = 0; l < 8; l++) {
        int lin = t + l * 128;
        int r = lin >> 4;
        int c4 = (lin & 15) * 4;
        *(float4*)&KVs[r][c4] = *(const float4*)(g_kv + (size_t)bh * (D_ * D_) + r * D_ + c4);
        float4 qx = *(const float4*)(g_q + (size_t)(b * NQ_ + n0 + r) * E_ + h * D_ + c4);
        float mu = mu_s[r], rstd = rstd_s[r];
        float y0 = (qx.x - mu) * rstd * gam_s[c4 + 0] + bet_s[c4 + 0];
        float y1 = (qx.y - mu) * rstd * gam_s[c4 + 1] + bet_s[c4 + 1];
        float y2 = (qx.z - mu) * rstd * gam_s[c4 + 2] + bet_s[c4 + 2];
        float y3 = (qx.w - mu) * rstd * gam_s[c4 + 3] + bet_s[c4 + 3];
        float4 qz;
        qz.x = (y0 > 0.0f) ? (y0 + 1.0f) : expf(y0);
        qz.y = (y1 > 0.0f) ? (y1 + 1.0f) : expf(y1);
        qz.z = (y2 > 0.0f) ? (y2 + 1.0f) : expf(y2);
        qz.w = (y3 > 0.0f) ? (y3 + 1.0f) : expf(y3);
        *(float4*)&Qs[r][c4] = qz;
    }
    __syncthreads();

    const int tx = t & 15;
    const int ty = t >> 4;
    float acc[8][4];
#pragma unroll
    for (int i = 0; i < 8; i++)
#pragma unroll
        for (int j = 0; j < 4; j++) acc[i][j] = 0.0f;

#pragma unroll 4
    for (int d = 0; d < 64; d++) {
        float bb[4];
        *(float4*)bb = *(const float4*)&KVs[d][tx * 4];
#pragma unroll
        for (int i = 0; i < 8; i++) {
            float a = Qs[ty * 8 + i][d];
#pragma unroll
            for (int j = 0; j < 4; j++) acc[i][j] += a * bb[j];
        }
    }

    float den[8];
#pragma unroll
    for (int i = 0; i < 8; i++) den[i] = 0.0f;
#pragma unroll 4
    for (int d = 0; d < 64; d++) {
        float kd = ksums[d];
#pragma unroll
        for (int i = 0; i < 8; i++) den[i] += Qs[ty * 8 + i][d] * kd;
    }

#pragma unroll
    for (int i = 0; i < 8; i++) {
        float inv = 1.0f / (den[i] + 1e-8f);
        int row = b * NQ_ + n0 + ty * 8 + i;
        float4 o;
        o.x = acc[i][0] * inv; o.y = acc[i][1] * inv;
        o.z = acc[i][2] * inv; o.w = acc[i][3] * inv;
        *(float4*)(g_attn + (size_t)row * E_ + h * D_ + tx * 4) = o;
    }
}

// ---------------- host launcher ----------------
extern "C" void kernel_launch(void* const* d_in, const int* in_sizes, int n_in,
                              void* d_out, int out_size) {
    (void)in_sizes; (void)n_in; (void)out_size;
    const float* query = (const float*)d_in[0];
    const float* key   = (const float*)d_in[1];
    const float* value = (const float*)d_in[2];
    const float* Wq = (const float*)d_in[3];
    const float* bq = (const float*)d_in[4];
    const float* Wk = (const float*)d_in[5];
    const float* bk = (const float*)d_in[6];
    const float* Wv = (const float*)d_in[7];
    const float* bv = (const float*)d_in[8];
    const float* Wo = (const float*)d_in[9];
    const float* bo = (const float*)d_in[10];
    const float* gq    = (const float*)d_in[11];
    const float* betaq = (const float*)d_in[12];
    const float* gk    = (const float*)d_in[13];
    const float* betak = (const float*)d_in[14];
    float* out = (float*)d_out;

    float *pq, *pk, *pv, *pattn, *pks, *pqs;
    cudaGetSymbolAddress((void**)&pq, g_q);
    cudaGetSymbolAddress((void**)&pk, g_k);
    cudaGetSymbolAddress((void**)&pv, g_v);
    cudaGetSymbolAddress((void**)&pattn, g_attn);
    cudaGetSymbolAddress((void**)&pks, g_kstats);
    cudaGetSymbolAddress((void**)&pqs, g_qstats);

    cudaFuncSetAttribute(gemm_plain_kernel,
                         cudaFuncAttributeMaxDynamicSharedMemorySize, GEMM_SMEM);
    cudaFuncSetAttribute(gemm_stats_kernel,
                         cudaFuncAttributeMaxDynamicSharedMemorySize, GEMM_SMEM);
    cudaFuncSetAttribute(gemm_stats_kv_kernel,
                         cudaFuncAttributeMaxDynamicSharedMemorySize, GEMM_SMEM);

    // zero LN-stat accumulators (graph-capturable async memset)
    cudaMemsetAsync(pks, 0, (size_t)2 * MTOT * sizeof(float));
    cudaMemsetAsync(pqs, 0, (size_t)2 * MTOT * sizeof(float));

    // L1: K projection + row stats
    gemm_stats_kernel<<<NGEMM_CTAS, 256, GEMM_SMEM>>>(key, Wk, bk, pk, pks);
    // L2: V projection
    gemm_plain_kernel<<<NGEMM_CTAS, 256, GEMM_SMEM>>>(value, Wv, bv, pv);
    // L3: Q projection + row stats ∥ KV split-K partials (LN+elu on K inline)
    gemm_stats_kv_kernel<<<NGEMM_CTAS + BH_ * NSPLIT, 256, GEMM_SMEM>>>(
        query, Wq, bq, pq, pqs, gk, betak);
    // L4: reduce split-K partials
    reduce_kv_kernel<<<(BH_ * D_ * D_ + BH_ * D_ + 255) / 256, 256>>>();
    // L5: attention apply (LN+elu on Q inline)
    attn_kernel<<<dim3(BH_, NQ_ / 64), 128>>>(gq, betaq);
    // L6: output projection -> d_out
    gemm_plain_kernel<<<NGEMM_CTAS, 256, GEMM_SMEM>>>(pattn, Wo, bo, out);
}

// round 12
// speedup vs baseline: 1.4856x; 1.4856x over previous
#include <cuda_runtime.h>
#include <cstdint>

// Problem constants
#define E_   1024
#define H_   16
#define D_   64
#define B_   4
#define NQ_  4096
#define NK_  4096
#define MTOT (B_*NQ_)      // 16384 rows for all projections
#define BH_  (B_*H_)       // 64
#define NSPLIT 32          // split-K partitions for KV reduction

// ---------------- scratch (device globals; no allocation APIs) ----------------
__device__ float g_q[(size_t)MTOT * E_];      // raw Q projection (pre-LN)
__device__ float g_k[(size_t)MTOT * E_];      // raw K projection (pre-LN)
__device__ float g_v[(size_t)MTOT * E_];
__device__ float g_attn[(size_t)MTOT * E_];
__device__ float g_kvp[(size_t)NSPLIT * BH_ * D_ * D_];
__device__ float g_ksp[(size_t)NSPLIT * BH_ * D_];
__device__ float g_kv[(size_t)BH_ * D_ * D_];
__device__ float g_ksum[(size_t)BH_ * D_];
__device__ float g_kstats[(size_t)2 * MTOT];  // per-row {sum, sumsq} of K proj
__device__ float g_qstats[(size_t)2 * MTOT];  // per-row {sum, sumsq} of Q proj

// =====================================================================
// Helpers (sm_80+ base target features only)
// =====================================================================
__device__ __forceinline__ uint32_t smem_u32(const void* p) {
    uint32_t a;
    asm("{ .reg .u64 t; cvta.to.shared.u64 t, %1; cvt.u32.u64 %0, t; }"
        : "=r"(a) : "l"(p));
    return a;
}

__device__ __forceinline__ void cp_async16(uint32_t saddr, const void* gaddr) {
    asm volatile("cp.async.cg.shared.global [%0], [%1], 16;"
                 :: "r"(saddr), "l"(gaddr));
}
__device__ __forceinline__ void cp_commit() {
    asm volatile("cp.async.commit_group;" ::: "memory");
}
template <int N>
__device__ __forceinline__ void cp_wait() {
    asm volatile("cp.async.wait_group %0;" :: "n"(N) : "memory");
}

__device__ __forceinline__ uint32_t f2tf32(float f) {
    uint32_t u;
    asm("cvt.rna.tf32.f32 %0, %1;" : "=r"(u) : "f"(f));
    return u;
}

__device__ __forceinline__ void mma_tf32(
    float& d0, float& d1, float& d2, float& d3,
    uint32_t a0, uint32_t a1, uint32_t a2, uint32_t a3,
    uint32_t b0, uint32_t b1)
{
    asm volatile(
        "mma.sync.aligned.m16n8k8.row.col.f32.tf32.tf32.f32 "
        "{%0,%1,%2,%3}, {%4,%5,%6,%7}, {%8,%9}, {%0,%1,%2,%3};"
        : "+f"(d0), "+f"(d1), "+f"(d2), "+f"(d3)
        : "r"(a0), "r"(a1), "r"(a2), "r"(a3), "r"(b0), "r"(b1));
}

// =====================================================================
// tf32 GEMM (round-7 kernel, byte-exact): C[m,n]=sum_k X[m,k]W[n,k]+bias[n]
// =====================================================================
#define BM 128
#define BN 128
#define BK 32
#define NKT (E_/BK)
#define ASTR 36
#define TILEF (128*ASTR)
#define GEMM_SMEM (4*TILEF*4)   // 73728 bytes

__global__ void __launch_bounds__(256, 2)
gemm_mma_kernel(const float* __restrict__ X, const float* __restrict__ W,
                const float* __restrict__ bias, float* __restrict__ C)
{
    extern __shared__ float smf[];
    const uint32_t sbase = smem_u32(smf);
    const int tid = threadIdx.x;
    const int wid = tid >> 5;
    const int lane = tid & 31;
    const int g  = lane >> 2;
    const int t4 = lane & 3;
    const int wm = (wid >> 2) * 64;
    const int wn = (wid & 3) * 32;
    const int bm = blockIdx.x * BM;
    const int bn = blockIdx.y * BN;

    const int srow = tid >> 3;
    const int sc4  = (tid & 7) * 4;

    float acc[4][4][4];
#pragma unroll
    for (int i = 0; i < 4; i++)
#pragma unroll
        for (int j = 0; j < 4; j++)
#pragma unroll
            for (int r = 0; r < 4; r++) acc[i][j][r] = 0.0f;

    auto prefetch = [&](int kt, int buf) {
        const int k0 = kt * BK;
        const uint32_t aoff = sbase + (uint32_t)(buf * TILEF) * 4u;
        const uint32_t boff = sbase + (uint32_t)((2 + buf) * TILEF) * 4u;
#pragma unroll
        for (int l = 0; l < 4; l++) {
            int row = srow + l * 32;
            cp_async16(aoff + (row * ASTR + sc4) * 4,
                       X + (size_t)(bm + row) * E_ + k0 + sc4);
            cp_async16(boff + (row * ASTR + sc4) * 4,
                       W + (size_t)(bn + row) * E_ + k0 + sc4);
        }
        cp_commit();
    };

    prefetch(0, 0);

    for (int kt = 0; kt < NKT; kt++) {
        const int buf = kt & 1;
        if (kt + 1 < NKT) {
            prefetch(kt + 1, buf ^ 1);
            cp_wait<1>();
        } else {
            cp_wait<0>();
        }
        __syncthreads();

        const float* As = smf + buf * TILEF;
        const float* Bs = smf + (2 + buf) * TILEF;

#pragma unroll
        for (int ks = 0; ks < 4; ks++) {
            const int kk = ks * 8;
            uint32_t bf[4][2];
#pragma unroll
            for (int nf = 0; nf < 4; nf++) {
                const float* bp = Bs + (wn + nf * 8 + g) * ASTR + kk + t4;
                bf[nf][0] = f2tf32(bp[0]);
                bf[nf][1] = f2tf32(bp[4]);
            }
#pragma unroll
            for (int mf = 0; mf < 4; mf++) {
                const float* ap = As + (wm + mf * 16 + g) * ASTR + kk + t4;
                uint32_t a0 = f2tf32(ap[0]);
                uint32_t a1 = f2tf32(ap[8 * ASTR]);
                uint32_t a2 = f2tf32(ap[4]);
                uint32_t a3 = f2tf32(ap[8 * ASTR + 4]);
#pragma unroll
                for (int nf = 0; nf < 4; nf++)
                    mma_tf32(acc[mf][nf][0], acc[mf][nf][1],
                             acc[mf][nf][2], acc[mf][nf][3],
                             a0, a1, a2, a3, bf[nf][0], bf[nf][1]);
            }
        }
        __syncthreads();
    }

#pragma unroll
    for (int nf = 0; nf < 4; nf++) {
        const int col = bn + wn + nf * 8 + t4 * 2;
        const float2 b2 = *(const float2*)(bias + col);
#pragma unroll
        for (int mf = 0; mf < 4; mf++) {
            const int row0 = bm + wm + mf * 16 + g;
            float2 v0, v1;
            v0.x = acc[mf][nf][0] + b2.x;
            v0.y = acc[mf][nf][1] + b2.y;
            v1.x = acc[mf][nf][2] + b2.x;
            v1.y = acc[mf][nf][3] + b2.y;
            *(float2*)(C + (size_t)row0 * E_ + col) = v0;
            *(float2*)(C + (size_t)(row0 + 8) * E_ + col) = v1;
        }
    }
}

// ---------------- row stats: {sum, sumsq} per row (read-only pass) ----------------
__global__ __launch_bounds__(256)
void row_stats_kernel(const float* __restrict__ X, float* __restrict__ stats)
{
    const int row = blockIdx.x;
    const int t = threadIdx.x;
    const float4 v = *(const float4*)(X + (size_t)row * E_ + t * 4);

    float s  = v.x + v.y + v.z + v.w;
    float sq = v.x * v.x + v.y * v.y + v.z * v.z + v.w * v.w;

    __shared__ float reds[8], redq[8];
#pragma unroll
    for (int o = 16; o > 0; o >>= 1) {
        s  += __shfl_xor_sync(0xffffffffu, s,  o);
        sq += __shfl_xor_sync(0xffffffffu, sq, o);
    }
    if ((t & 31) == 0) { reds[t >> 5] = s; redq[t >> 5] = sq; }
    __syncthreads();
    if (t == 0) {
        float ts = 0.0f, tq = 0.0f;
#pragma unroll
        for (int i = 0; i < 8; i++) { ts += reds[i]; tq += redq[i]; }
        stats[2 * row + 0] = ts;
        stats[2 * row + 1] = tq;
    }
}

// ---------------- KV reduction with inline LN+elu on K ----------------
__global__ __launch_bounds__(256)
void kv_kernel(const float* __restrict__ gk, const float* __restrict__ betak)
{
    const int bh = blockIdx.x;
    const int b = bh >> 4, h = bh & 15;
    const int split = blockIdx.y;
    const int t = threadIdx.x;
    const int tx = t & 15, ty = t >> 4;

    __shared__ float Ks[64][68];
    __shared__ float Vs[64][68];
    __shared__ float mu_s[64], rstd_s[64], gam_s[64], bet_s[64];

    const float* kbase = g_k + (size_t)(b * NK_) * E_ + h * D_;
    const float* vbase = g_v + (size_t)(b * NK_) * E_ + h * D_;

    if (t < 64) {
        gam_s[t] = gk[h * D_ + t];
        bet_s[t] = betak[h * D_ + t];
    }

    float acc[4][4];
#pragma unroll
    for (int i = 0; i < 4; i++)
#pragma unroll
        for (int j = 0; j < 4; j++) acc[i][j] = 0.0f;
    float ks_local = 0.0f;

    for (int sblk = 0; sblk < 2; sblk++) {
        int n0 = split * 128 + sblk * 64;
        if (t < 64) {
            int row = b * NK_ + n0 + t;
            float s = g_kstats[2 * row + 0];
            float q = g_kstats[2 * row + 1];
            float mu = s * (1.0f / E_);
            float var = q * (1.0f / E_) - mu * mu;
            mu_s[t] = mu;
            rstd_s[t] = rsqrtf(var + 1e-5f);
        }
        __syncthreads();
#pragma unroll
        for (int l = 0; l < 4; l++) {
            int lin = t + l * 256;
            int r = lin >> 4;
            int c4 = (lin & 15) * 4;
            float4 kx = *(const float4*)(kbase + (size_t)(n0 + r) * E_ + c4);
            float mu = mu_s[r], rstd = rstd_s[r];
            float y0 = (kx.x - mu) * rstd * gam_s[c4 + 0] + bet_s[c4 + 0];
            float y1 = (kx.y - mu) * rstd * gam_s[c4 + 1] + bet_s[c4 + 1];
            float y2 = (kx.z - mu) * rstd * gam_s[c4 + 2] + bet_s[c4 + 2];
            float y3 = (kx.w - mu) * rstd * gam_s[c4 + 3] + bet_s[c4 + 3];
            float4 kz;
            kz.x = (y0 > 0.0f) ? (y0 + 1.0f) : expf(y0);
            kz.y = (y1 > 0.0f) ? (y1 + 1.0f) : expf(y1);
            kz.z = (y2 > 0.0f) ? (y2 + 1.0f) : expf(y2);
            kz.w = (y3 > 0.0f) ? (y3 + 1.0f) : expf(y3);
            *(float4*)&Ks[r][c4] = kz;
            *(float4*)&Vs[r][c4] = *(const float4*)(vbase + (size_t)(n0 + r) * E_ + c4);
        }
        __syncthreads();
#pragma unroll 4
        for (int n = 0; n < 64; n++) {
            float a[4], bb[4];
            *(float4*)a  = *(const float4*)&Ks[n][ty * 4];
            *(float4*)bb = *(const float4*)&Vs[n][tx * 4];
#pragma unroll
            for (int i = 0; i < 4; i++)
#pragma unroll
                for (int j = 0; j < 4; j++)
                    acc[i][j] += a[i] * bb[j];
        }
        if (t < 64) {
            float ss = 0.0f;
#pragma unroll 4
            for (int n = 0; n < 64; n++) ss += Ks[n][t];
            ks_local += ss;
        }
        __syncthreads();
    }

    float* outp = g_kvp + ((size_t)(split * BH_ + bh)) * (D_ * D_);
#pragma unroll
    for (int i = 0; i < 4; i++)
#pragma unroll
        for (int j = 0; j < 4; j++)
            outp[(ty * 4 + i) * D_ + tx * 4 + j] = acc[i][j];
    if (t < 64) g_ksp[(size_t)(split * BH_ + bh) * D_ + t] = ks_local;
}

// ---------------- reduce split-K partials ----------------
__global__ __launch_bounds__(256)
void reduce_kv_kernel() {
    int idx = blockIdx.x * blockDim.x + threadIdx.x;
    const int NKV = BH_ * D_ * D_;
    const int NKS = BH_ * D_;
    if (idx < NKV) {
        float s = 0.0f;
#pragma unroll
        for (int sp = 0; sp < NSPLIT; sp++)
            s += g_kvp[(size_t)sp * NKV + idx];
        g_kv[idx] = s;
    } else if (idx < NKV + NKS) {
        int j = idx - NKV;
        float s = 0.0f;
#pragma unroll
        for (int sp = 0; sp < NSPLIT; sp++)
            s += g_ksp[(size_t)sp * NKS + j];
        g_ksum[j] = s;
    }
}

// ---------------- attention apply with inline LN+elu on Q ----------------
// Block: 256 threads, 128 query rows of one (b,h)  (halves g_kv re-reads).
__global__ __launch_bounds__(256)
void attn_kernel(const float* __restrict__ gq, const float* __restrict__ betaq)
{
    const int bh = blockIdx.x;
    const int b = bh >> 4, h = bh & 15;
    const int n0 = blockIdx.y * 128;
    const int t = threadIdx.x;

    __shared__ float Qs[128][68];
    __shared__ float KVs[64][68];
    __shared__ float ksums[64];
    __shared__ float mu_s[128], rstd_s[128], gam_s[64], bet_s[64];

    if (t < 64) {
        gam_s[t] = gq[h * D_ + t];
        bet_s[t] = betaq[h * D_ + t];
        ksums[t] = g_ksum[(size_t)bh * D_ + t];
    }
    if (t < 128) {
        int row = b * NQ_ + n0 + t;
        float s = g_qstats[2 * row + 0];
        float q = g_qstats[2 * row + 1];
        float mu = s * (1.0f / E_);
        float var = q * (1.0f / E_) - mu * mu;
        mu_s[t] = mu;
        rstd_s[t] = rsqrtf(var + 1e-5f);
    }
    __syncthreads();

    // KV tile: 64x64 = 1024 float4 -> 4 per thread
#pragma unroll
    for (int l = 0; l < 4; l++) {
        int lin = t + l * 256;
        int r = lin >> 4;
        int c4 = (lin & 15) * 4;
        *(float4*)&KVs[r][c4] = *(const float4*)(g_kv + (size_t)bh * (D_ * D_) + r * D_ + c4);
    }
    // Q tile: 128 rows x 16 float4 -> 8 per thread, LN+elu inline
#pragma unroll
    for (int l = 0; l < 8; l++) {
        int lin = t + l * 256;
        int r = lin >> 4;
        int c4 = (lin & 15) * 4;
        float4 qx = *(const float4*)(g_q + (size_t)(b * NQ_ + n0 + r) * E_ + h * D_ + c4);
        float mu = mu_s[r], rstd = rstd_s[r];
        float y0 = (qx.x - mu) * rstd * gam_s[c4 + 0] + bet_s[c4 + 0];
        float y1 = (qx.y - mu) * rstd * gam_s[c4 + 1] + bet_s[c4 + 1];
        float y2 = (qx.z - mu) * rstd * gam_s[c4 + 2] + bet_s[c4 + 2];
        float y3 = (qx.w - mu) * rstd * gam_s[c4 + 3] + bet_s[c4 + 3];
        float4 qz;
        qz.x = (y0 > 0.0f) ? (y0 + 1.0f) : expf(y0);
        qz.y = (y1 > 0.0f) ? (y1 + 1.0f) : expf(y1);
        qz.z = (y2 > 0.0f) ? (y2 + 1.0f) : expf(y2);
        qz.w = (y3 > 0.0f) ? (y3 + 1.0f) : expf(y3);
        *(float4*)&Qs[r][c4] = qz;
    }
    __syncthreads();

    const int tx = t & 15;   // 4 output cols
    const int ty = t >> 4;   // 16 groups x 8 rows = 128 rows
    float acc[8][4];
#pragma unroll
    for (int i = 0; i < 8; i++)
#pragma unroll
        for (int j = 0; j < 4; j++) acc[i][j] = 0.0f;

#pragma unroll 4
    for (int d = 0; d < 64; d++) {
        float bb[4];
        *(float4*)bb = *(const float4*)&KVs[d][tx * 4];
#pragma unroll
        for (int i = 0; i < 8; i++) {
            float a = Qs[ty * 8 + i][d];
#pragma unroll
            for (int j = 0; j < 4; j++) acc[i][j] += a * bb[j];
        }
    }

    float den[8];
#pragma unroll
    for (int i = 0; i < 8; i++) den[i] = 0.0f;
#pragma unroll 4
    for (int d = 0; d < 64; d++) {
        float kd = ksums[d];
#pragma unroll
        for (int i = 0; i < 8; i++) den[i] += Qs[ty * 8 + i][d] * kd;
    }

#pragma unroll
    for (int i = 0; i < 8; i++) {
        float inv = 1.0f / (den[i] + 1e-8f);
        int row = b * NQ_ + n0 + ty * 8 + i;
        float4 o;
        o.x = acc[i][0] * inv; o.y = acc[i][1] * inv;
        o.z = acc[i][2] * inv; o.w = acc[i][3] * inv;
        *(float4*)(g_attn + (size_t)row * E_ + h * D_ + tx * 4) = o;
    }
}

// ---------------- host launcher ----------------
extern "C" void kernel_launch(void* const* d_in, const int* in_sizes, int n_in,
                              void* d_out, int out_size) {
    (void)in_sizes; (void)n_in; (void)out_size;
    const float* query = (const float*)d_in[0];
    const float* key   = (const float*)d_in[1];
    const float* value = (const float*)d_in[2];
    const float* Wq = (const float*)d_in[3];
    const float* bq = (const float*)d_in[4];
    const float* Wk = (const float*)d_in[5];
    const float* bk = (const float*)d_in[6];
    const float* Wv = (const float*)d_in[7];
    const float* bv = (const float*)d_in[8];
    const float* Wo = (const float*)d_in[9];
    const float* bo = (const float*)d_in[10];
    const float* gq    = (const float*)d_in[11];
    const float* betaq = (const float*)d_in[12];
    const float* gk    = (const float*)d_in[13];
    const float* betak = (const float*)d_in[14];
    float* out = (float*)d_out;

    float *pq, *pk, *pv, *pattn, *pks, *pqs;
    cudaGetSymbolAddress((void**)&pq, g_q);
    cudaGetSymbolAddress((void**)&pk, g_k);
    cudaGetSymbolAddress((void**)&pv, g_v);
    cudaGetSymbolAddress((void**)&pattn, g_attn);
    cudaGetSymbolAddress((void**)&pks, g_kstats);
    cudaGetSymbolAddress((void**)&pqs, g_qstats);

    cudaFuncSetAttribute(gemm_mma_kernel,
                         cudaFuncAttributeMaxDynamicSharedMemorySize, GEMM_SMEM);

    dim3 ggrid(MTOT / BM, E_ / BN);   // (128, 8)

    // K projection, then its row stats (read-only pass)
    gemm_mma_kernel<<<ggrid, 256, GEMM_SMEM>>>(key, Wk, bk, pk);
    row_stats_kernel<<<MTOT, 256>>>(pk, pks);
    // V projection
    gemm_mma_kernel<<<ggrid, 256, GEMM_SMEM>>>(value, Wv, bv, pv);
    // KV split-K partials (LN+elu on K applied inline)
    kv_kernel<<<dim3(BH_, NSPLIT), 256>>>(gk, betak);
    // Q projection, then its row stats
    gemm_mma_kernel<<<ggrid, 256, GEMM_SMEM>>>(query, Wq, bq, pq);
    row_stats_kernel<<<MTOT, 256>>>(pq, pqs);
    // reduce split-K partials
    reduce_kv_kernel<<<(BH_ * D_ * D_ + BH_ * D_ + 255) / 256, 256>>>();
    // attention apply (LN+elu on Q applied inline)
    attn_kernel<<<dim3(BH_, NQ_ / 128), 256>>>(gq, betaq);
    // output projection -> d_out
    gemm_mma_kernel<<<ggrid, 256, GEMM_SMEM>>>(pattn, Wo, bo, out);
}

// round 13
// speedup vs baseline: 1.5689x; 1.0561x over previous
#include <cuda_runtime.h>
#include <cstdint>

// Problem constants
#define E_   1024
#define H_   16
#define D_   64
#define B_   4
#define NQ_  4096
#define NK_  4096
#define MTOT (B_*NQ_)      // 16384 rows for all projections
#define BH_  (B_*H_)       // 64
#define NSPLIT 16          // split-K partitions for KV reduction

// ---------------- scratch (device globals; no allocation APIs) ----------------
__device__ float g_q[(size_t)MTOT * E_];      // Q projection (LN+elu'd in place)
__device__ float g_k[(size_t)MTOT * E_];      // K projection (LN+elu'd in place)
__device__ float g_v[(size_t)MTOT * E_];
__device__ float g_attn[(size_t)MTOT * E_];
__device__ float g_kvp[(size_t)NSPLIT * BH_ * D_ * D_];
__device__ float g_ksp[(size_t)NSPLIT * BH_ * D_];
__device__ float g_kv[(size_t)BH_ * D_ * D_];
__device__ float g_ksum[(size_t)BH_ * D_];

// =====================================================================
// Helpers (sm_80+ base target features only)
// =====================================================================
__device__ __forceinline__ uint32_t smem_u32(const void* p) {
    uint32_t a;
    asm("{ .reg .u64 t; cvta.to.shared.u64 t, %1; cvt.u32.u64 %0, t; }"
        : "=r"(a) : "l"(p));
    return a;
}

__device__ __forceinline__ void cp_async16(uint32_t saddr, const void* gaddr) {
    asm volatile("cp.async.cg.shared.global [%0], [%1], 16;"
                 :: "r"(saddr), "l"(gaddr));
}
__device__ __forceinline__ void cp_commit() {
    asm volatile("cp.async.commit_group;" ::: "memory");
}
template <int N>
__device__ __forceinline__ void cp_wait() {
    asm volatile("cp.async.wait_group %0;" :: "n"(N) : "memory");
}

__device__ __forceinline__ uint32_t f2tf32(float f) {
    uint32_t u;
    asm("cvt.rna.tf32.f32 %0, %1;" : "=r"(u) : "f"(f));
    return u;
}

__device__ __forceinline__ void mma_tf32(
    float& d0, float& d1, float& d2, float& d3,
    uint32_t a0, uint32_t a1, uint32_t a2, uint32_t a3,
    uint32_t b0, uint32_t b1)
{
    asm volatile(
        "mma.sync.aligned.m16n8k8.row.col.f32.tf32.tf32.f32 "
        "{%0,%1,%2,%3}, {%4,%5,%6,%7}, {%8,%9}, {%0,%1,%2,%3};"
        : "+f"(d0), "+f"(d1), "+f"(d2), "+f"(d3)
        : "r"(a0), "r"(a1), "r"(a2), "r"(a3), "r"(b0), "r"(b1));
}

// =====================================================================
// tf32 GEMM (round-7 kernel, byte-exact): C[m,n]=sum_k X[m,k]W[n,k]+bias[n]
// =====================================================================
#define BM 128
#define BN 128
#define BK 32
#define NKT (E_/BK)
#define ASTR 36
#define TILEF (128*ASTR)
#define GEMM_SMEM (4*TILEF*4)   // 73728 bytes

__global__ void __launch_bounds__(256, 2)
gemm_mma_kernel(const float* __restrict__ X, const float* __restrict__ W,
                const float* __restrict__ bias, float* __restrict__ C)
{
    extern __shared__ float smf[];
    const uint32_t sbase = smem_u32(smf);
    const int tid = threadIdx.x;
    const int wid = tid >> 5;
    const int lane = tid & 31;
    const int g  = lane >> 2;
    const int t4 = lane & 3;
    const int wm = (wid >> 2) * 64;
    const int wn = (wid & 3) * 32;
    const int bm = blockIdx.x * BM;
    const int bn = blockIdx.y * BN;

    const int srow = tid >> 3;
    const int sc4  = (tid & 7) * 4;

    float acc[4][4][4];
#pragma unroll
    for (int i = 0; i < 4; i++)
#pragma unroll
        for (int j = 0; j < 4; j++)
#pragma unroll
            for (int r = 0; r < 4; r++) acc[i][j][r] = 0.0f;

    auto prefetch = [&](int kt, int buf) {
        const int k0 = kt * BK;
        const uint32_t aoff = sbase + (uint32_t)(buf * TILEF) * 4u;
        const uint32_t boff = sbase + (uint32_t)((2 + buf) * TILEF) * 4u;
#pragma unroll
        for (int l = 0; l < 4; l++) {
            int row = srow + l * 32;
            cp_async16(aoff + (row * ASTR + sc4) * 4,
                       X + (size_t)(bm + row) * E_ + k0 + sc4);
            cp_async16(boff + (row * ASTR + sc4) * 4,
                       W + (size_t)(bn + row) * E_ + k0 + sc4);
        }
        cp_commit();
    };

    prefetch(0, 0);

    for (int kt = 0; kt < NKT; kt++) {
        const int buf = kt & 1;
        if (kt + 1 < NKT) {
            prefetch(kt + 1, buf ^ 1);
            cp_wait<1>();
        } else {
            cp_wait<0>();
        }
        __syncthreads();

        const float* As = smf + buf * TILEF;
        const float* Bs = smf + (2 + buf) * TILEF;

#pragma unroll
        for (int ks = 0; ks < 4; ks++) {
            const int kk = ks * 8;
            uint32_t bf[4][2];
#pragma unroll
            for (int nf = 0; nf < 4; nf++) {
                const float* bp = Bs + (wn + nf * 8 + g) * ASTR + kk + t4;
                bf[nf][0] = f2tf32(bp[0]);
                bf[nf][1] = f2tf32(bp[4]);
            }
#pragma unroll
            for (int mf = 0; mf < 4; mf++) {
                const float* ap = As + (wm + mf * 16 + g) * ASTR + kk + t4;
                uint32_t a0 = f2tf32(ap[0]);
                uint32_t a1 = f2tf32(ap[8 * ASTR]);
                uint32_t a2 = f2tf32(ap[4]);
                uint32_t a3 = f2tf32(ap[8 * ASTR + 4]);
#pragma unroll
                for (int nf = 0; nf < 4; nf++)
                    mma_tf32(acc[mf][nf][0], acc[mf][nf][1],
                             acc[mf][nf][2], acc[mf][nf][3],
                             a0, a1, a2, a3, bf[nf][0], bf[nf][1]);
            }
        }
        __syncthreads();
    }

#pragma unroll
    for (int nf = 0; nf < 4; nf++) {
        const int col = bn + wn + nf * 8 + t4 * 2;
        const float2 b2 = *(const float2*)(bias + col);
#pragma unroll
        for (int mf = 0; mf < 4; mf++) {
            const int row0 = bm + wm + mf * 16 + g;
            float2 v0, v1;
            v0.x = acc[mf][nf][0] + b2.x;
            v0.y = acc[mf][nf][1] + b2.y;
            v1.x = acc[mf][nf][2] + b2.x;
            v1.y = acc[mf][nf][3] + b2.y;
            *(float2*)(C + (size_t)row0 * E_ + col) = v0;
            *(float2*)(C + (size_t)(row0 + 8) * E_ + col) = v1;
        }
    }
}

// ---------------- LayerNorm + elu + 1, in place, one block per row ----------------
__global__ __launch_bounds__(256)
void ln_elu_kernel(float* __restrict__ X, const float* __restrict__ gamma,
                   const float* __restrict__ beta) {
    const int row = blockIdx.x;
    const int t = threadIdx.x;
    float* xr = X + (size_t)row * E_;

    float v[4];
#pragma unroll
    for (int i = 0; i < 4; i++) v[i] = xr[t + i * 256];

    __shared__ float red[8];
    float s = v[0] + v[1] + v[2] + v[3];
#pragma unroll
    for (int o = 16; o > 0; o >>= 1) s += __shfl_xor_sync(0xffffffffu, s, o);
    if ((t & 31) == 0) red[t >> 5] = s;
    __syncthreads();
    float tot = red[0] + red[1] + red[2] + red[3] + red[4] + red[5] + red[6] + red[7];
    float mean = tot * (1.0f / E_);
    __syncthreads();

    float d0 = v[0] - mean, d1 = v[1] - mean, d2 = v[2] - mean, d3 = v[3] - mean;
    float s2 = d0 * d0 + d1 * d1 + d2 * d2 + d3 * d3;
#pragma unroll
    for (int o = 16; o > 0; o >>= 1) s2 += __shfl_xor_sync(0xffffffffu, s2, o);
    if ((t & 31) == 0) red[t >> 5] = s2;
    __syncthreads();
    float var = (red[0] + red[1] + red[2] + red[3] + red[4] + red[5] + red[6] + red[7]) * (1.0f / E_);
    float rstd = rsqrtf(var + 1e-5f);

    float dd[4] = {d0, d1, d2, d3};
#pragma unroll
    for (int i = 0; i < 4; i++) {
        int col = t + i * 256;
        float y = dd[i] * rstd * gamma[col] + beta[col];
        xr[col] = (y > 0.0f) ? (y + 1.0f) : expf(y);
    }
}

// =====================================================================
// KV reduction via tensor cores:
// per (b,h): KV[d][e] = sum_n K'[n][d] * V[n][e]; ksum[d] = sum_n K'[n][d]
// grid (BH, NSPLIT); CTA handles 256 n-rows as 4 tiles of 64.
// 8 warps: (2 in M=d) x (2 in N=e) x (2 k-halves), combined via SMEM.
// =====================================================================
#define KVCH (NK_/NSPLIT)   // 256
#define KSTR 65

__global__ void __launch_bounds__(256)
kv_mma_kernel()
{
    __shared__ float sm[2 * 64 * KSTR];   // KsT | VsT (also reused as combine buf)
    float* KsT = sm;
    float* VsT = sm + 64 * KSTR;

    const int bh = blockIdx.x;
    const int b = bh >> 4, h = bh & 15;
    const int split = blockIdx.y;
    const int t = threadIdx.x;
    const int wid = t >> 5, lane = t & 31;
    const int g = lane >> 2, t4 = lane & 3;
    const int wn = (wid & 1) * 32;
    const int wm = ((wid >> 1) & 1) * 32;
    const int kh = wid >> 2;             // k-half within each 64-n tile

    const float* kbase = g_k + (size_t)(b * NK_) * E_ + h * D_;
    const float* vbase = g_v + (size_t)(b * NK_) * E_ + h * D_;

    float acc[2][4][4];
#pragma unroll
    for (int i = 0; i < 2; i++)
#pragma unroll
        for (int j = 0; j < 4; j++)
#pragma unroll
            for (int r = 0; r < 4; r++) acc[i][j][r] = 0.0f;
    float ksl = 0.0f;

    for (int tile = 0; tile < KVCH / 64; tile++) {
        const int n0 = split * KVCH + tile * 64;
        // load 64x64 K' and V tiles, store transposed: KsT[d][n], VsT[e][n]
#pragma unroll
        for (int l = 0; l < 4; l++) {
            int lin = t + l * 256;
            int r = lin >> 4;             // n within tile
            int c4 = (lin & 15) * 4;      // d/e quad
            float4 kx = *(const float4*)(kbase + (size_t)(n0 + r) * E_ + c4);
            KsT[(c4 + 0) * KSTR + r] = kx.x;
            KsT[(c4 + 1) * KSTR + r] = kx.y;
            KsT[(c4 + 2) * KSTR + r] = kx.z;
            KsT[(c4 + 3) * KSTR + r] = kx.w;
            float4 vx = *(const float4*)(vbase + (size_t)(n0 + r) * E_ + c4);
            VsT[(c4 + 0) * KSTR + r] = vx.x;
            VsT[(c4 + 1) * KSTR + r] = vx.y;
            VsT[(c4 + 2) * KSTR + r] = vx.z;
            VsT[(c4 + 3) * KSTR + r] = vx.w;
        }
        __syncthreads();

#pragma unroll
        for (int ks = 0; ks < 4; ks++) {
            const int kk = kh * 32 + ks * 8;
            uint32_t bf[4][2];
#pragma unroll
            for (int nf = 0; nf < 4; nf++) {
                const float* bp = &VsT[(wn + nf * 8 + g) * KSTR + kk + t4];
                bf[nf][0] = f2tf32(bp[0]);
                bf[nf][1] = f2tf32(bp[4]);
            }
#pragma unroll
            for (int mf = 0; mf < 2; mf++) {
                const float* ap = &KsT[(wm + mf * 16 + g) * KSTR + kk + t4];
                uint32_t a0 = f2tf32(ap[0]);
                uint32_t a1 = f2tf32(ap[8 * KSTR]);
                uint32_t a2 = f2tf32(ap[4]);
                uint32_t a3 = f2tf32(ap[8 * KSTR + 4]);
#pragma unroll
                for (int nf = 0; nf < 4; nf++)
                    mma_tf32(acc[mf][nf][0], acc[mf][nf][1],
                             acc[mf][nf][2], acc[mf][nf][3],
                             a0, a1, a2, a3, bf[nf][0], bf[nf][1]);
            }
        }
        // ksum: thread t<64 owns d=t; K' tile still live in SMEM
        if (t < 64) {
            float ss = 0.0f;
#pragma unroll 4
            for (int n = 0; n < 64; n++) ss += KsT[t * KSTR + n];
            ksl += ss;
        }
        __syncthreads();
    }

    // combine the two k-halves: kh=1 warps stage to SMEM (stride 66), kh=0 add
    float* buf = sm;
    if (kh == 1) {
#pragma unroll
        for (int mf = 0; mf < 2; mf++)
#pragma unroll
            for (int nf = 0; nf < 4; nf++) {
                int d0 = wm + mf * 16 + g;
                int e0 = wn + nf * 8 + t4 * 2;
                buf[d0 * 66 + e0]           = acc[mf][nf][0];
                buf[d0 * 66 + e0 + 1]       = acc[mf][nf][1];
                buf[(d0 + 8) * 66 + e0]     = acc[mf][nf][2];
                buf[(d0 + 8) * 66 + e0 + 1] = acc[mf][nf][3];
            }
    }
    __syncthreads();
    if (kh == 0) {
        float* outp = g_kvp + (size_t)(split * BH_ + bh) * (D_ * D_);
#pragma unroll
        for (int mf = 0; mf < 2; mf++)
#pragma unroll
            for (int nf = 0; nf < 4; nf++) {
                int d0 = wm + mf * 16 + g;
                int e0 = wn + nf * 8 + t4 * 2;
                float2 w0, w1;
                w0.x = acc[mf][nf][0] + buf[d0 * 66 + e0];
                w0.y = acc[mf][nf][1] + buf[d0 * 66 + e0 + 1];
                w1.x = acc[mf][nf][2] + buf[(d0 + 8) * 66 + e0];
                w1.y = acc[mf][nf][3] + buf[(d0 + 8) * 66 + e0 + 1];
                *(float2*)(outp + d0 * D_ + e0) = w0;
                *(float2*)(outp + (d0 + 8) * D_ + e0) = w1;
            }
    }
    if (t < 64)
        g_ksp[(size_t)(split * BH_ + bh) * D_ + t] = ksl;
}

// ---------------- reduce split-K partials ----------------
__global__ __launch_bounds__(256)
void reduce_kv_kernel() {
    int idx = blockIdx.x * blockDim.x + threadIdx.x;
    const int NKV = BH_ * D_ * D_;
    const int NKS = BH_ * D_;
    if (idx < NKV) {
        float s = 0.0f;
#pragma unroll
        for (int sp = 0; sp < NSPLIT; sp++)
            s += g_kvp[(size_t)sp * NKV + idx];
        g_kv[idx] = s;
    } else if (idx < NKV + NKS) {
        int j = idx - NKV;
        float s = 0.0f;
#pragma unroll
        for (int sp = 0; sp < NSPLIT; sp++)
            s += g_ksp[(size_t)sp * NKS + j];
        g_ksum[j] = s;
    }
}

// =====================================================================
// Attention apply via tensor cores:
// per (b,h), 64-row q-tile: num = Q'[64x64] @ KV[64x64], den = Q'.ksum
// 8 warps: 4 in M (16 rows) x 2 in N (32 cols); k-dim = d (8 steps).
// =====================================================================
#define QSTR 68

__global__ void __launch_bounds__(256)
attn_mma_kernel()
{
    __shared__ float Qs[64 * QSTR];
    __shared__ float KVT[64 * QSTR];
    __shared__ float ksums[64];

    const int bh = blockIdx.x;
    const int b = bh >> 4, h = bh & 15;
    const int n0 = blockIdx.y * 64;
    const int t = threadIdx.x;
    const int wid = t >> 5, lane = t & 31;
    const int g = lane >> 2, t4 = lane & 3;
    const int wq = wid >> 1;             // M group: rows wq*16 .. wq*16+15
    const int wn = (wid & 1) * 32;       // N half

    if (t < 64) ksums[t] = g_ksum[(size_t)bh * D_ + t];

    // Q' tile 64x64, row-major (already LN+elu'd in g_q)
#pragma unroll
    for (int l = 0; l < 4; l++) {
        int lin = t + l * 256;
        int r = lin >> 4;
        int c4 = (lin & 15) * 4;
        *(float4*)&Qs[r * QSTR + c4] =
            *(const float4*)(g_q + (size_t)(b * NQ_ + n0 + r) * E_ + h * D_ + c4);
    }
    // KV transposed: KVT[e][d] = g_kv[bh][d][e]
#pragma unroll
    for (int l = 0; l < 4; l++) {
        int lin = t + l * 256;
        int rd = lin >> 4;            // d
        int c4 = (lin & 15) * 4;      // e quad
        float4 kvx = *(const float4*)(g_kv + (size_t)bh * (D_ * D_) + rd * D_ + c4);
        KVT[(c4 + 0) * QSTR + rd] = kvx.x;
        KVT[(c4 + 1) * QSTR + rd] = kvx.y;
        KVT[(c4 + 2) * QSTR + rd] = kvx.z;
        KVT[(c4 + 3) * QSTR + rd] = kvx.w;
    }
    __syncthreads();

    float acc[4][4];
#pragma unroll
    for (int j = 0; j < 4; j++)
#pragma unroll
        for (int r = 0; r < 4; r++) acc[j][r] = 0.0f;

#pragma unroll
    for (int ks = 0; ks < 8; ks++) {
        const int kk = ks * 8;
        const float* ap = &Qs[(wq * 16 + g) * QSTR + kk + t4];
        uint32_t a0 = f2tf32(ap[0]);
        uint32_t a1 = f2tf32(ap[8 * QSTR]);
        uint32_t a2 = f2tf32(ap[4]);
        uint32_t a3 = f2tf32(ap[8 * QSTR + 4]);
#pragma unroll
        for (int nf = 0; nf < 4; nf++) {
            const float* bp = &KVT[(wn + nf * 8 + g) * QSTR + kk + t4];
            mma_tf32(acc[nf][0], acc[nf][1], acc[nf][2], acc[nf][3],
                     a0, a1, a2, a3, f2tf32(bp[0]), f2tf32(bp[4]));
        }
    }

    // denominator: rows r0, r1; lanes split d-range by t4, shuffle-combine
    const int r0 = wq * 16 + g, r1 = r0 + 8;
    float dp0 = 0.0f, dp1 = 0.0f;
#pragma unroll
    for (int i = 0; i < 16; i++) {
        int d = t4 * 16 + i;
        float kd = ksums[d];
        dp0 += Qs[r0 * QSTR + d] * kd;
        dp1 += Qs[r1 * QSTR + d] * kd;
    }
    dp0 += __shfl_xor_sync(0xffffffffu, dp0, 1);
    dp0 += __shfl_xor_sync(0xffffffffu, dp0, 2);
    dp1 += __shfl_xor_sync(0xffffffffu, dp1, 1);
    dp1 += __shfl_xor_sync(0xffffffffu, dp1, 2);
    const float inv0 = 1.0f / (dp0 + 1e-8f);
    const float inv1 = 1.0f / (dp1 + 1e-8f);

#pragma unroll
    for (int nf = 0; nf < 4; nf++) {
        const int e0 = wn + nf * 8 + t4 * 2;
        float2 o0, o1;
        o0.x = acc[nf][0] * inv0; o0.y = acc[nf][1] * inv0;
        o1.x = acc[nf][2] * inv1; o1.y = acc[nf][3] * inv1;
        *(float2*)(g_attn + (size_t)(b * NQ_ + n0 + r0) * E_ + h * D_ + e0) = o0;
        *(float2*)(g_attn + (size_t)(b * NQ_ + n0 + r1) * E_ + h * D_ + e0) = o1;
    }
}

// ---------------- host launcher ----------------
extern "C" void kernel_launch(void* const* d_in, const int* in_sizes, int n_in,
                              void* d_out, int out_size) {
    (void)in_sizes; (void)n_in; (void)out_size;
    const float* query = (const float*)d_in[0];
    const float* key   = (const float*)d_in[1];
    const float* value = (const float*)d_in[2];
    const float* Wq = (const float*)d_in[3];
    const float* bq = (const float*)d_in[4];
    const float* Wk = (const float*)d_in[5];
    const float* bk = (const float*)d_in[6];
    const float* Wv = (const float*)d_in[7];
    const float* bv = (const float*)d_in[8];
    const float* Wo = (const float*)d_in[9];
    const float* bo = (const float*)d_in[10];
    const float* gq    = (const float*)d_in[11];
    const float* betaq = (const float*)d_in[12];
    const float* gk    = (const float*)d_in[13];
    const float* betak = (const float*)d_in[14];
    float* out = (float*)d_out;

    float *pq, *pk, *pv, *pattn;
    cudaGetSymbolAddress((void**)&pq, g_q);
    cudaGetSymbolAddress((void**)&pk, g_k);
    cudaGetSymbolAddress((void**)&pv, g_v);
    cudaGetSymbolAddress((void**)&pattn, g_attn);

    cudaFuncSetAttribute(gemm_mma_kernel,
                         cudaFuncAttributeMaxDynamicSharedMemorySize, GEMM_SMEM);

    dim3 ggrid(MTOT / BM, E_ / BN);   // (128, 8)

    // K projection + LN+elu (in place)
    gemm_mma_kernel<<<ggrid, 256, GEMM_SMEM>>>(key, Wk, bk, pk);
    ln_elu_kernel<<<MTOT, 256>>>(pk, gk, betak);
    // V projection
    gemm_mma_kernel<<<ggrid, 256, GEMM_SMEM>>>(value, Wv, bv, pv);
    // KV split-K partials (tensor-core)
    kv_mma_kernel<<<dim3(BH_, NSPLIT), 256>>>();
    // Q projection + LN+elu (in place)
    gemm_mma_kernel<<<ggrid, 256, GEMM_SMEM>>>(query, Wq, bq, pq);
    ln_elu_kernel<<<MTOT, 256>>>(pq, gq, betaq);
    // reduce split-K partials
    reduce_kv_kernel<<<(BH_ * D_ * D_ + BH_ * D_ + 255) / 256, 256>>>();
    // attention apply (tensor-core)
    attn_mma_kernel<<<dim3(BH_, NQ_ / 64), 256>>>();
    // output projection -> d_out
    gemm_mma_kernel<<<ggrid, 256, GEMM_SMEM>>>(pattn, Wo, bo, out);
}